// round 14
// baseline (speedup 1.0000x reference)
#include <cuda_runtime.h>
#include <cuda_fp16.h>
#include <cstdint>

// RGCN basis layer, scatter-first ordering (round-10 structure):
//   agg[v, b, :] = sum_{e: dst=v} (w_comp[etype_e, b] * norm_e) * h[src_e]
//   out = relu( [agg | h] @ [W0;W1;W2;W3;loop_w] + bias )
// Stages:
//   prep:   h->fp16, Wh fp16 n-major stack, zero counts+total
//   hist:   per-dst counts + per-edge rank (4 edges/thread)
//   scan:   block-local exclusive scan + atomic block base
//   bucket: ONE 16B record {src, c01h, c23h} per edge (2 edges/thread, full occ)
//   accum:  warp/dst register accumulation -> agg fp16 (.nc gathers, .cs stores)
//   gemm2:  fp16 mma m16n8k16, 128x128 tile, 2-stage cp.async, 2 blocks/SM

#define HD 128
#define NB 4
#define NNODES 50000
#define NEDGES 800000
#define NP 50176            // 392 * 128 = 196 * 256
#define NBLK 196
#define KTOT 640
#define SMSH 72             // smem row stride in halves (144B) -> conflict-free

__device__ __half g_h16[(size_t)NP * HD];        // 12.8 MB
__device__ __half g_agg[(size_t)NP * 512];       // 51.4 MB
__device__ __half g_Wh[HD * KTOT];               // fp16 n-major weights

// CSR scratch
__device__ int  g_cnt[NP];
__device__ int  g_off[NP];
__device__ int  g_total;
__device__ int  g_rank[NEDGES];
__device__ int4 g_edge[NEDGES];    // {src, c01(half2), c23(half2), pad}

static __device__ __forceinline__ uint32_t smem_u32(const void* p) {
    uint32_t a;
    asm("{ .reg .u64 t; cvta.to.shared.u64 t, %1; cvt.u32.u64 %0, t; }" : "=r"(a) : "l"(p));
    return a;
}

#define CP_ASYNC8(sa, gp) \
    asm volatile("cp.async.ca.shared.global [%0], [%1], 8;" :: "r"(sa), "l"(gp))
#define CP_COMMIT() asm volatile("cp.async.commit_group;")

struct alignas(8) Half4 { __half2 lo, hi; };

static __device__ __forceinline__ int h2_as_int(__half2 h) { return *(int*)&h; }
static __device__ __forceinline__ __half2 int_as_h2(int i) { return *(__half2*)&i; }

// non-coherent 8B load (read-only path)
static __device__ __forceinline__ Half4 ldg_nc_h4(const __half* p) {
    uint2 u;
    asm("ld.global.nc.v2.u32 {%0, %1}, [%2];" : "=r"(u.x), "=r"(u.y) : "l"(p));
    Half4 r;
    r.lo = int_as_h2((int)u.x);
    r.hi = int_as_h2((int)u.y);
    return r;
}
// non-coherent 16B load
static __device__ __forceinline__ int4 ldg_nc_i4(const int4* p) {
    int4 v;
    asm("ld.global.nc.v4.s32 {%0, %1, %2, %3}, [%4];"
        : "=r"(v.x), "=r"(v.y), "=r"(v.z), "=r"(v.w) : "l"(p));
    return v;
}
// evict-first 8B store
static __device__ __forceinline__ void stg_cs_h4(__half* p, Half4 v) {
    uint2 u;
    u.x = (uint32_t)h2_as_int(v.lo);
    u.y = (uint32_t)h2_as_int(v.hi);
    asm volatile("st.global.cs.v2.u32 [%0], {%1, %2};" :: "l"(p), "r"(u.x), "r"(u.y));
}

// ---------------------------------------------------------------------------
// prep: h16 convert + weight stack + zero counts
// ---------------------------------------------------------------------------
__global__ __launch_bounds__(256) void prep_k(
    const float* __restrict__ h,
    const float* __restrict__ basis_w,
    const float* __restrict__ loop_w,
    int M)
{
    int idx = blockIdx.x * blockDim.x + threadIdx.x;

    if (idx < NP * 32) {
        int m = idx >> 5;
        float4 v = (m < M) ? *(const float4*)(h + (size_t)idx * 4)
                           : make_float4(0.f, 0.f, 0.f, 0.f);
        Half4 o;
        o.lo = __floats2half2_rn(v.x, v.y);
        o.hi = __floats2half2_rn(v.z, v.w);
        *(Half4*)(g_h16 + (size_t)idx * 4) = o;
    }
    if (idx < HD * KTOT) {          // Wh[n][k]
        int n = idx / KTOT;
        int k = idx - n * KTOT;
        float v;
        if (k < NB * HD) {
            int b = k >> 7, kk = k & 127;
            v = basis_w[(size_t)b * HD * HD + (size_t)kk * HD + n];
        } else {
            v = loop_w[(size_t)(k - NB * HD) * HD + n];
        }
        g_Wh[idx] = __float2half_rn(v);
    }
    if (idx < NP) g_cnt[idx] = 0;
    if (idx == 0) g_total = 0;
}

// ---------------------------------------------------------------------------
// hist: counts + per-edge rank, 4 edges/thread
// ---------------------------------------------------------------------------
__global__ __launch_bounds__(256) void hist_k(const int* __restrict__ dst, int E)
{
    int e0 = (blockIdx.x * blockDim.x + threadIdx.x) * 4;
    if (e0 + 3 < E) {
        int4 d = *(const int4*)(dst + e0);
        int r0 = atomicAdd(&g_cnt[d.x], 1);
        int r1 = atomicAdd(&g_cnt[d.y], 1);
        int r2 = atomicAdd(&g_cnt[d.z], 1);
        int r3 = atomicAdd(&g_cnt[d.w], 1);
        *(int4*)(g_rank + e0) = make_int4(r0, r1, r2, r3);
    } else {
        for (int e = e0; e < E; e++)
            g_rank[e] = atomicAdd(&g_cnt[dst[e]], 1);
    }
}

// ---------------------------------------------------------------------------
// scan: block-local exclusive scan; base via atomicAdd (order arbitrary)
// ---------------------------------------------------------------------------
__global__ __launch_bounds__(256) void scan_k()
{
    __shared__ int s[256];
    __shared__ int blockBase;
    int t = threadIdx.x;
    int gid = blockIdx.x * 256 + t;
    int v = g_cnt[gid];
    s[t] = v;
    __syncthreads();
    #pragma unroll
    for (int d = 1; d < 256; d <<= 1) {
        int x = (t >= d) ? s[t - d] : 0;
        __syncthreads();
        s[t] += x;
        __syncthreads();
    }
    if (t == 255) blockBase = atomicAdd(&g_total, s[255]);
    __syncthreads();
    g_off[gid] = blockBase + s[t] - v;
}

// ---------------------------------------------------------------------------
// bucket: one 16B record per edge, 2 edges/thread (full occupancy)
// ---------------------------------------------------------------------------
__global__ __launch_bounds__(256) void bucket_k(
    const float* __restrict__ w_comp,
    const float* __restrict__ norm,
    const int* __restrict__ src,
    const int* __restrict__ dst,
    const int* __restrict__ etype,
    int E)
{
    int e0 = (blockIdx.x * blockDim.x + threadIdx.x) * 2;
    if (e0 + 1 < E) {
        int2   d  = *(const int2*)(dst + e0);
        int2   sc = *(const int2*)(src + e0);
        int2   tt = *(const int2*)(etype + e0);
        float2 nm = *(const float2*)(norm + e0);
        int2   rk = *(const int2*)(g_rank + e0);
        // gather both offsets first (MLP 2)
        int o0 = g_off[d.x];
        int o1 = g_off[d.y];
        {
            const float* wr = w_comp + tt.x * NB;
            __half2 c01 = __floats2half2_rn(wr[0] * nm.x, wr[1] * nm.x);
            __half2 c23 = __floats2half2_rn(wr[2] * nm.x, wr[3] * nm.x);
            g_edge[o0 + rk.x] = make_int4(sc.x, h2_as_int(c01), h2_as_int(c23), 0);
        }
        {
            const float* wr = w_comp + tt.y * NB;
            __half2 c01 = __floats2half2_rn(wr[0] * nm.y, wr[1] * nm.y);
            __half2 c23 = __floats2half2_rn(wr[2] * nm.y, wr[3] * nm.y);
            g_edge[o1 + rk.y] = make_int4(sc.y, h2_as_int(c01), h2_as_int(c23), 0);
        }
    } else {
        for (int e = e0; e < E; e++) {
            int dd = dst[e];
            const float* wr = w_comp + etype[e] * NB;
            float nmv = norm[e];
            __half2 c01 = __floats2half2_rn(wr[0] * nmv, wr[1] * nmv);
            __half2 c23 = __floats2half2_rn(wr[2] * nmv, wr[3] * nmv);
            g_edge[g_off[dd] + g_rank[e]] =
                make_int4(src[e], h2_as_int(c01), h2_as_int(c23), 0);
        }
    }
}

// ---------------------------------------------------------------------------
// accum: warp per dst node; 16 fp32 acc regs/lane; 4-edge unroll (MLP 4).
// Read-only data via ld.global.nc; agg stream-out via st.global.cs.
// ---------------------------------------------------------------------------
__global__ __launch_bounds__(256) void accum_k()
{
    int v    = (blockIdx.x * blockDim.x + threadIdx.x) >> 5;
    int lane = threadIdx.x & 31;
    if (v >= NP) return;

    int base = g_off[v];
    int deg  = g_cnt[v];

    float4 a0 = {0.f, 0.f, 0.f, 0.f};
    float4 a1 = a0, a2 = a0, a3 = a0;

    const __half* Hl = g_h16 + lane * 4;

    int i = 0;
    for (; i + 4 <= deg; i += 4) {
        int4 r0 = ldg_nc_i4(&g_edge[base + i]);
        int4 r1 = ldg_nc_i4(&g_edge[base + i + 1]);
        int4 r2 = ldg_nc_i4(&g_edge[base + i + 2]);
        int4 r3 = ldg_nc_i4(&g_edge[base + i + 3]);
        Half4 hv0 = ldg_nc_h4(Hl + (size_t)r0.x * HD);
        Half4 hv1 = ldg_nc_h4(Hl + (size_t)r1.x * HD);
        Half4 hv2 = ldg_nc_h4(Hl + (size_t)r2.x * HD);
        Half4 hv3 = ldg_nc_h4(Hl + (size_t)r3.x * HD);
        #pragma unroll
        for (int j = 0; j < 4; j++) {
            int4 rr = (j == 0) ? r0 : (j == 1) ? r1 : (j == 2) ? r2 : r3;
            Half4 hh = (j == 0) ? hv0 : (j == 1) ? hv1 : (j == 2) ? hv2 : hv3;
            float2 c01 = __half22float2(int_as_h2(rr.y));
            float2 c23 = __half22float2(int_as_h2(rr.z));
            float2 lo = __half22float2(hh.lo), hi = __half22float2(hh.hi);
            a0.x += c01.x * lo.x; a0.y += c01.x * lo.y; a0.z += c01.x * hi.x; a0.w += c01.x * hi.y;
            a1.x += c01.y * lo.x; a1.y += c01.y * lo.y; a1.z += c01.y * hi.x; a1.w += c01.y * hi.y;
            a2.x += c23.x * lo.x; a2.y += c23.x * lo.y; a2.z += c23.x * hi.x; a2.w += c23.x * hi.y;
            a3.x += c23.y * lo.x; a3.y += c23.y * lo.y; a3.z += c23.y * hi.x; a3.w += c23.y * hi.y;
        }
    }
    for (; i < deg; i++) {
        int4 rr = ldg_nc_i4(&g_edge[base + i]);
        Half4 hh = ldg_nc_h4(Hl + (size_t)rr.x * HD);
        float2 c01 = __half22float2(int_as_h2(rr.y));
        float2 c23 = __half22float2(int_as_h2(rr.z));
        float2 lo = __half22float2(hh.lo), hi = __half22float2(hh.hi);
        a0.x += c01.x * lo.x; a0.y += c01.x * lo.y; a0.z += c01.x * hi.x; a0.w += c01.x * hi.y;
        a1.x += c01.y * lo.x; a1.y += c01.y * lo.y; a1.z += c01.y * hi.x; a1.w += c01.y * hi.y;
        a2.x += c23.x * lo.x; a2.y += c23.x * lo.y; a2.z += c23.x * hi.x; a2.w += c23.x * hi.y;
        a3.x += c23.y * lo.x; a3.y += c23.y * lo.y; a3.z += c23.y * hi.x; a3.w += c23.y * hi.y;
    }

    __half* ap = g_agg + (size_t)v * 512 + lane * 4;
    Half4 o;
    o.lo = __floats2half2_rn(a0.x, a0.y); o.hi = __floats2half2_rn(a0.z, a0.w);
    stg_cs_h4(ap + 0, o);
    o.lo = __floats2half2_rn(a1.x, a1.y); o.hi = __floats2half2_rn(a1.z, a1.w);
    stg_cs_h4(ap + 128, o);
    o.lo = __floats2half2_rn(a2.x, a2.y); o.hi = __floats2half2_rn(a2.z, a2.w);
    stg_cs_h4(ap + 256, o);
    o.lo = __floats2half2_rn(a3.x, a3.y); o.hi = __floats2half2_rn(a3.z, a3.w);
    stg_cs_h4(ap + 384, o);
}

// ---------------------------------------------------------------------------
// gemm2: fp16 mma m16n8k16, 2-stage cp.async pipeline, 2 blocks/SM.
// Block 128m x 128n, K=640 in 64-chunks; 8 warps = 4m x 2n.
// ---------------------------------------------------------------------------
#define STAGE_HALVES (2 * 128 * SMSH)              // A + B per stage
#define STAGE_BYTES  (STAGE_HALVES * 2)
#define SMEM_BYTES   (2 * STAGE_BYTES)             // 73728

__global__ __launch_bounds__(256, 2) void gemm2_k(
    const float* __restrict__ bias,
    float* __restrict__ out,
    int M)
{
    extern __shared__ __half smh[];

    const int tid  = threadIdx.x;
    const int m0   = blockIdx.x * 128;
    const int lane = tid & 31;
    const int w    = tid >> 5;
    const int wm   = w & 3;
    const int wn   = w >> 2;

    const int fr = tid >> 4;     // 0..15 base row, step 16
    const int fq = tid & 15;     // Half4 quad in 64-half chunk row

    uint32_t sA0 = smem_u32(smh) + (uint32_t)(fr * SMSH + fq * 4) * 2;
    uint32_t sB0 = sA0 + (uint32_t)(128 * SMSH) * 2;

    auto fill = [&](int kc, int s) {
        uint32_t sa = sA0 + s * STAGE_BYTES;
        uint32_t sb = sB0 + s * STAGE_BYTES;
        if (kc < 8) {
            const __half* ap = g_agg + (size_t)(m0 + fr) * 512 + kc * 64 + fq * 4;
            #pragma unroll
            for (int i = 0; i < 8; i++)
                CP_ASYNC8(sa + i * 16 * SMSH * 2, ap + (size_t)i * 16 * 512);
        } else {
            const __half* ap = g_h16 + (size_t)(m0 + fr) * HD + (kc * 64 - 512) + fq * 4;
            #pragma unroll
            for (int i = 0; i < 8; i++)
                CP_ASYNC8(sa + i * 16 * SMSH * 2, ap + (size_t)i * 16 * HD);
        }
        const __half* bp = g_Wh + (size_t)fr * KTOT + kc * 64 + fq * 4;
        #pragma unroll
        for (int i = 0; i < 8; i++)
            CP_ASYNC8(sb + i * 16 * SMSH * 2, bp + (size_t)i * 16 * KTOT);
        CP_COMMIT();
    };

    const int arow  = (lane & 7) + ((lane >> 3) & 1) * 8;
    const int akoff = (lane & 16) ? 8 : 0;
    const int brow  = (lane & 7) + ((lane & 16) ? 8 : 0);
    const int bkoff = (lane & 8) ? 8 : 0;

    uint32_t aAddr[2], bAddr[4];
    #pragma unroll
    for (int mt = 0; mt < 2; mt++)
        aAddr[mt] = smem_u32(smh + (wm * 32 + mt * 16 + arow) * SMSH + akoff);
    #pragma unroll
    for (int p = 0; p < 4; p++)
        bAddr[p] = smem_u32(smh + 128 * SMSH + (wn * 64 + p * 16 + brow) * SMSH + bkoff);

    float acc[2][8][4];
    #pragma unroll
    for (int mt = 0; mt < 2; mt++)
        #pragma unroll
        for (int nt = 0; nt < 8; nt++)
            #pragma unroll
            for (int q = 0; q < 4; q++) acc[mt][nt][q] = 0.f;

    fill(0, 0);
    fill(1, 1);

    for (int kc = 0; kc < 10; kc++) {
        int s = kc & 1;
        if (kc == 9) { asm volatile("cp.async.wait_group 0;"); }
        else         { asm volatile("cp.async.wait_group 1;"); }
        __syncthreads();

        uint32_t soff = (uint32_t)s * STAGE_BYTES;
        #pragma unroll
        for (int k0 = 0; k0 < 64; k0 += 16) {
            uint32_t a[2][4], b[4][4];
            #pragma unroll
            for (int mt = 0; mt < 2; mt++)
                asm volatile("ldmatrix.sync.aligned.m8n8.x4.shared.b16 {%0,%1,%2,%3}, [%4];"
                             : "=r"(a[mt][0]), "=r"(a[mt][1]), "=r"(a[mt][2]), "=r"(a[mt][3])
                             : "r"(aAddr[mt] + soff + k0 * 2));
            #pragma unroll
            for (int p = 0; p < 4; p++)
                asm volatile("ldmatrix.sync.aligned.m8n8.x4.shared.b16 {%0,%1,%2,%3}, [%4];"
                             : "=r"(b[p][0]), "=r"(b[p][1]), "=r"(b[p][2]), "=r"(b[p][3])
                             : "r"(bAddr[p] + soff + k0 * 2));
            #pragma unroll
            for (int mt = 0; mt < 2; mt++)
                #pragma unroll
                for (int nt = 0; nt < 8; nt++) {
                    int p = nt >> 1, q = (nt & 1) * 2;
                    asm volatile(
                        "mma.sync.aligned.m16n8k16.row.col.f32.f16.f16.f32 "
                        "{%0,%1,%2,%3}, {%4,%5,%6,%7}, {%8,%9}, {%0,%1,%2,%3};"
                        : "+f"(acc[mt][nt][0]), "+f"(acc[mt][nt][1]),
                          "+f"(acc[mt][nt][2]), "+f"(acc[mt][nt][3])
                        : "r"(a[mt][0]), "r"(a[mt][1]), "r"(a[mt][2]), "r"(a[mt][3]),
                          "r"(b[p][q]), "r"(b[p][q + 1]));
                }
        }
        __syncthreads();
        if (kc + 2 < 10) fill(kc + 2, s);
    }

    // ---- epilogue: bias + relu ----
    const int rbase = lane >> 2;
    const int col2  = (lane & 3) * 2;
    #pragma unroll
    for (int mt = 0; mt < 2; mt++) {
        #pragma unroll
        for (int hh = 0; hh < 2; hh++) {
            int gm = m0 + wm * 32 + mt * 16 + rbase + hh * 8;
            if (gm >= M) continue;
            #pragma unroll
            for (int nt = 0; nt < 8; nt++) {
                int gn = wn * 64 + nt * 8 + col2;
                float2 o;
                o.x = fmaxf(acc[mt][nt][hh * 2]     + bias[gn],     0.f);
                o.y = fmaxf(acc[mt][nt][hh * 2 + 1] + bias[gn + 1], 0.f);
                *(float2*)(out + (size_t)gm * HD + gn) = o;
            }
        }
    }
}

extern "C" void kernel_launch(void* const* d_in, const int* in_sizes, int n_in,
                              void* d_out, int out_size)
{
    const float* h       = (const float*)d_in[0];
    const float* norm    = (const float*)d_in[1];
    const float* basis_w = (const float*)d_in[2];
    const float* w_comp  = (const float*)d_in[3];
    const float* loop_w  = (const float*)d_in[4];
    const float* bias    = (const float*)d_in[5];
    const int*   src     = (const int*)d_in[6];
    const int*   dst     = (const int*)d_in[7];
    const int*   etype   = (const int*)d_in[8];
    float* out = (float*)d_out;

    int M = in_sizes[0] / HD;   // 50000
    int E = in_sizes[6];        // 800000

    cudaFuncSetAttribute(gemm2_k, cudaFuncAttributeMaxDynamicSharedMemorySize, SMEM_BYTES);

    prep_k<<<(NP * 32 + 255) / 256, 256>>>(h, basis_w, loop_w, M);
    hist_k<<<((E + 3) / 4 + 255) / 256, 256>>>(dst, E);
    scan_k<<<NBLK, 256>>>();
    bucket_k<<<((E + 1) / 2 + 255) / 256, 256>>>(w_comp, norm, src, dst, etype, E);
    accum_k<<<(NP * 32 + 255) / 256, 256>>>();
    gemm2_k<<<NP / 128, 256, SMEM_BYTES>>>(bias, out, M);
}

// round 15
// speedup vs baseline: 1.1092x; 1.1092x over previous
#include <cuda_runtime.h>
#include <cuda_fp16.h>
#include <cstdint>

// RGCN basis layer, scatter-first ordering (round-10 structure; 8B edge records):
//   agg[v, b, :] = sum_{e: dst=v} (w_comp[etype_e, b] * norm_e) * h[src_e]
//   out = relu( [agg | h] @ [W0;W1;W2;W3;loop_w] + bias )
// Stages:
//   prep:   h->fp16, Wh fp16 n-major stack, zero counts+total
//   hist:   per-dst counts + per-edge rank (4 edges/thread)
//   scan:   block-local exclusive scan + atomic block base
//   bucket: ONE 8B record {src|etype<<16, norm_f32} per edge (2 edges/thread)
//   accum:  warp/dst register accumulation; w_comp in smem; coeffs fp32
//   gemm2:  fp16 mma m16n8k16, 128x128 tile, 2-stage cp.async, 2 blocks/SM

#define HD 128
#define NB 4
#define NREL 40
#define NNODES 50000
#define NEDGES 800000
#define NP 50176            // 392 * 128 = 196 * 256
#define NBLK 196
#define KTOT 640
#define SMSH 72             // smem row stride in halves (144B) -> conflict-free

__device__ __half g_h16[(size_t)NP * HD];        // 12.8 MB
__device__ __half g_agg[(size_t)NP * 512];       // 51.4 MB
__device__ __half g_Wh[HD * KTOT];               // fp16 n-major weights

// CSR scratch
__device__ int  g_cnt[NP];
__device__ int  g_off[NP];
__device__ int  g_total;
__device__ int  g_rank[NEDGES];
__device__ int2 g_edge8[NEDGES];   // {src | etype<<16, norm bits}

static __device__ __forceinline__ uint32_t smem_u32(const void* p) {
    uint32_t a;
    asm("{ .reg .u64 t; cvta.to.shared.u64 t, %1; cvt.u32.u64 %0, t; }" : "=r"(a) : "l"(p));
    return a;
}

#define CP_ASYNC8(sa, gp) \
    asm volatile("cp.async.ca.shared.global [%0], [%1], 8;" :: "r"(sa), "l"(gp))
#define CP_COMMIT() asm volatile("cp.async.commit_group;")

struct alignas(8) Half4 { __half2 lo, hi; };

// ---------------------------------------------------------------------------
// prep: h16 convert + weight stack + zero counts
// ---------------------------------------------------------------------------
__global__ __launch_bounds__(256) void prep_k(
    const float* __restrict__ h,
    const float* __restrict__ basis_w,
    const float* __restrict__ loop_w,
    int M)
{
    int idx = blockIdx.x * blockDim.x + threadIdx.x;

    if (idx < NP * 32) {
        int m = idx >> 5;
        float4 v = (m < M) ? *(const float4*)(h + (size_t)idx * 4)
                           : make_float4(0.f, 0.f, 0.f, 0.f);
        Half4 o;
        o.lo = __floats2half2_rn(v.x, v.y);
        o.hi = __floats2half2_rn(v.z, v.w);
        *(Half4*)(g_h16 + (size_t)idx * 4) = o;
    }
    if (idx < HD * KTOT) {          // Wh[n][k]
        int n = idx / KTOT;
        int k = idx - n * KTOT;
        float v;
        if (k < NB * HD) {
            int b = k >> 7, kk = k & 127;
            v = basis_w[(size_t)b * HD * HD + (size_t)kk * HD + n];
        } else {
            v = loop_w[(size_t)(k - NB * HD) * HD + n];
        }
        g_Wh[idx] = __float2half_rn(v);
    }
    if (idx < NP) g_cnt[idx] = 0;
    if (idx == 0) g_total = 0;
}

// ---------------------------------------------------------------------------
// hist: counts + per-edge rank, 4 edges/thread
// ---------------------------------------------------------------------------
__global__ __launch_bounds__(256) void hist_k(const int* __restrict__ dst, int E)
{
    int e0 = (blockIdx.x * blockDim.x + threadIdx.x) * 4;
    if (e0 + 3 < E) {
        int4 d = *(const int4*)(dst + e0);
        int r0 = atomicAdd(&g_cnt[d.x], 1);
        int r1 = atomicAdd(&g_cnt[d.y], 1);
        int r2 = atomicAdd(&g_cnt[d.z], 1);
        int r3 = atomicAdd(&g_cnt[d.w], 1);
        *(int4*)(g_rank + e0) = make_int4(r0, r1, r2, r3);
    } else {
        for (int e = e0; e < E; e++)
            g_rank[e] = atomicAdd(&g_cnt[dst[e]], 1);
    }
}

// ---------------------------------------------------------------------------
// scan: block-local exclusive scan; base via atomicAdd (order arbitrary)
// ---------------------------------------------------------------------------
__global__ __launch_bounds__(256) void scan_k()
{
    __shared__ int s[256];
    __shared__ int blockBase;
    int t = threadIdx.x;
    int gid = blockIdx.x * 256 + t;
    int v = g_cnt[gid];
    s[t] = v;
    __syncthreads();
    #pragma unroll
    for (int d = 1; d < 256; d <<= 1) {
        int x = (t >= d) ? s[t - d] : 0;
        __syncthreads();
        s[t] += x;
        __syncthreads();
    }
    if (t == 255) blockBase = atomicAdd(&g_total, s[255]);
    __syncthreads();
    g_off[gid] = blockBase + s[t] - v;
}

// ---------------------------------------------------------------------------
// bucket: one 8B record {src|etype<<16, norm bits} per edge, 2 edges/thread
// ---------------------------------------------------------------------------
__global__ __launch_bounds__(256) void bucket_k(
    const float* __restrict__ norm,
    const int* __restrict__ src,
    const int* __restrict__ dst,
    const int* __restrict__ etype,
    int E)
{
    int e0 = (blockIdx.x * blockDim.x + threadIdx.x) * 2;
    if (e0 + 1 < E) {
        int2   d  = *(const int2*)(dst + e0);
        int2   sc = *(const int2*)(src + e0);
        int2   tt = *(const int2*)(etype + e0);
        float2 nm = *(const float2*)(norm + e0);
        int2   rk = *(const int2*)(g_rank + e0);
        int o0 = g_off[d.x];
        int o1 = g_off[d.y];
        g_edge8[o0 + rk.x] = make_int2(sc.x | (tt.x << 16), __float_as_int(nm.x));
        g_edge8[o1 + rk.y] = make_int2(sc.y | (tt.y << 16), __float_as_int(nm.y));
    } else {
        for (int e = e0; e < E; e++) {
            int dd = dst[e];
            g_edge8[g_off[dd] + g_rank[e]] =
                make_int2(src[e] | (etype[e] << 16), __float_as_int(norm[e]));
        }
    }
}

// ---------------------------------------------------------------------------
// accum: warp per dst node; w_comp in smem; fp32 coeffs; 4-edge unroll.
// ---------------------------------------------------------------------------
__global__ __launch_bounds__(256) void accum_k(const float* __restrict__ w_comp)
{
    __shared__ float ws[NREL * NB];
    if (threadIdx.x < NREL * NB) ws[threadIdx.x] = w_comp[threadIdx.x];
    __syncthreads();

    int v    = (blockIdx.x * blockDim.x + threadIdx.x) >> 5;
    int lane = threadIdx.x & 31;
    if (v >= NP) return;

    int base = g_off[v];
    int deg  = g_cnt[v];

    float4 a0 = {0.f, 0.f, 0.f, 0.f};
    float4 a1 = a0, a2 = a0, a3 = a0;

    const __half* Hl = g_h16 + lane * 4;

    int i = 0;
    for (; i + 4 <= deg; i += 4) {
        int2 r0 = g_edge8[base + i];
        int2 r1 = g_edge8[base + i + 1];
        int2 r2 = g_edge8[base + i + 2];
        int2 r3 = g_edge8[base + i + 3];
        Half4 hv0 = *(const Half4*)(Hl + (size_t)(r0.x & 0xFFFF) * HD);
        Half4 hv1 = *(const Half4*)(Hl + (size_t)(r1.x & 0xFFFF) * HD);
        Half4 hv2 = *(const Half4*)(Hl + (size_t)(r2.x & 0xFFFF) * HD);
        Half4 hv3 = *(const Half4*)(Hl + (size_t)(r3.x & 0xFFFF) * HD);
        #pragma unroll
        for (int j = 0; j < 4; j++) {
            int2 rr = (j == 0) ? r0 : (j == 1) ? r1 : (j == 2) ? r2 : r3;
            Half4 hh = (j == 0) ? hv0 : (j == 1) ? hv1 : (j == 2) ? hv2 : hv3;
            int t = rr.x >> 16;
            float nm = __int_as_float(rr.y);
            const float* wr = ws + t * NB;
            float c0 = wr[0] * nm, c1 = wr[1] * nm, c2 = wr[2] * nm, c3 = wr[3] * nm;
            float2 lo = __half22float2(hh.lo), hi = __half22float2(hh.hi);
            a0.x += c0 * lo.x; a0.y += c0 * lo.y; a0.z += c0 * hi.x; a0.w += c0 * hi.y;
            a1.x += c1 * lo.x; a1.y += c1 * lo.y; a1.z += c1 * hi.x; a1.w += c1 * hi.y;
            a2.x += c2 * lo.x; a2.y += c2 * lo.y; a2.z += c2 * hi.x; a2.w += c2 * hi.y;
            a3.x += c3 * lo.x; a3.y += c3 * lo.y; a3.z += c3 * hi.x; a3.w += c3 * hi.y;
        }
    }
    for (; i < deg; i++) {
        int2 rr = g_edge8[base + i];
        Half4 hh = *(const Half4*)(Hl + (size_t)(rr.x & 0xFFFF) * HD);
        int t = rr.x >> 16;
        float nm = __int_as_float(rr.y);
        const float* wr = ws + t * NB;
        float c0 = wr[0] * nm, c1 = wr[1] * nm, c2 = wr[2] * nm, c3 = wr[3] * nm;
        float2 lo = __half22float2(hh.lo), hi = __half22float2(hh.hi);
        a0.x += c0 * lo.x; a0.y += c0 * lo.y; a0.z += c0 * hi.x; a0.w += c0 * hi.y;
        a1.x += c1 * lo.x; a1.y += c1 * lo.y; a1.z += c1 * hi.x; a1.w += c1 * hi.y;
        a2.x += c2 * lo.x; a2.y += c2 * lo.y; a2.z += c2 * hi.x; a2.w += c2 * hi.y;
        a3.x += c3 * lo.x; a3.y += c3 * lo.y; a3.z += c3 * hi.x; a3.w += c3 * hi.y;
    }

    __half* ap = g_agg + (size_t)v * 512 + lane * 4;
    Half4 o;
    o.lo = __floats2half2_rn(a0.x, a0.y); o.hi = __floats2half2_rn(a0.z, a0.w);
    *(Half4*)(ap + 0)   = o;
    o.lo = __floats2half2_rn(a1.x, a1.y); o.hi = __floats2half2_rn(a1.z, a1.w);
    *(Half4*)(ap + 128) = o;
    o.lo = __floats2half2_rn(a2.x, a2.y); o.hi = __floats2half2_rn(a2.z, a2.w);
    *(Half4*)(ap + 256) = o;
    o.lo = __floats2half2_rn(a3.x, a3.y); o.hi = __floats2half2_rn(a3.z, a3.w);
    *(Half4*)(ap + 384) = o;
}

// ---------------------------------------------------------------------------
// gemm2: fp16 mma m16n8k16, 2-stage cp.async pipeline, 2 blocks/SM.
// Block 128m x 128n, K=640 in 64-chunks; 8 warps = 4m x 2n.
// ---------------------------------------------------------------------------
#define STAGE_HALVES (2 * 128 * SMSH)              // A + B per stage
#define STAGE_BYTES  (STAGE_HALVES * 2)
#define SMEM_BYTES   (2 * STAGE_BYTES)             // 73728

__global__ __launch_bounds__(256, 2) void gemm2_k(
    const float* __restrict__ bias,
    float* __restrict__ out,
    int M)
{
    extern __shared__ __half smh[];

    const int tid  = threadIdx.x;
    const int m0   = blockIdx.x * 128;
    const int lane = tid & 31;
    const int w    = tid >> 5;
    const int wm   = w & 3;
    const int wn   = w >> 2;

    const int fr = tid >> 4;     // 0..15 base row, step 16
    const int fq = tid & 15;     // Half4 quad in 64-half chunk row

    uint32_t sA0 = smem_u32(smh) + (uint32_t)(fr * SMSH + fq * 4) * 2;
    uint32_t sB0 = sA0 + (uint32_t)(128 * SMSH) * 2;

    auto fill = [&](int kc, int s) {
        uint32_t sa = sA0 + s * STAGE_BYTES;
        uint32_t sb = sB0 + s * STAGE_BYTES;
        if (kc < 8) {
            const __half* ap = g_agg + (size_t)(m0 + fr) * 512 + kc * 64 + fq * 4;
            #pragma unroll
            for (int i = 0; i < 8; i++)
                CP_ASYNC8(sa + i * 16 * SMSH * 2, ap + (size_t)i * 16 * 512);
        } else {
            const __half* ap = g_h16 + (size_t)(m0 + fr) * HD + (kc * 64 - 512) + fq * 4;
            #pragma unroll
            for (int i = 0; i < 8; i++)
                CP_ASYNC8(sa + i * 16 * SMSH * 2, ap + (size_t)i * 16 * HD);
        }
        const __half* bp = g_Wh + (size_t)fr * KTOT + kc * 64 + fq * 4;
        #pragma unroll
        for (int i = 0; i < 8; i++)
            CP_ASYNC8(sb + i * 16 * SMSH * 2, bp + (size_t)i * 16 * KTOT);
        CP_COMMIT();
    };

    const int arow  = (lane & 7) + ((lane >> 3) & 1) * 8;
    const int akoff = (lane & 16) ? 8 : 0;
    const int brow  = (lane & 7) + ((lane & 16) ? 8 : 0);
    const int bkoff = (lane & 8) ? 8 : 0;

    uint32_t aAddr[2], bAddr[4];
    #pragma unroll
    for (int mt = 0; mt < 2; mt++)
        aAddr[mt] = smem_u32(smh + (wm * 32 + mt * 16 + arow) * SMSH + akoff);
    #pragma unroll
    for (int p = 0; p < 4; p++)
        bAddr[p] = smem_u32(smh + 128 * SMSH + (wn * 64 + p * 16 + brow) * SMSH + bkoff);

    float acc[2][8][4];
    #pragma unroll
    for (int mt = 0; mt < 2; mt++)
        #pragma unroll
        for (int nt = 0; nt < 8; nt++)
            #pragma unroll
            for (int q = 0; q < 4; q++) acc[mt][nt][q] = 0.f;

    fill(0, 0);
    fill(1, 1);

    for (int kc = 0; kc < 10; kc++) {
        int s = kc & 1;
        if (kc == 9) { asm volatile("cp.async.wait_group 0;"); }
        else         { asm volatile("cp.async.wait_group 1;"); }
        __syncthreads();

        uint32_t soff = (uint32_t)s * STAGE_BYTES;
        #pragma unroll
        for (int k0 = 0; k0 < 64; k0 += 16) {
            uint32_t a[2][4], b[4][4];
            #pragma unroll
            for (int mt = 0; mt < 2; mt++)
                asm volatile("ldmatrix.sync.aligned.m8n8.x4.shared.b16 {%0,%1,%2,%3}, [%4];"
                             : "=r"(a[mt][0]), "=r"(a[mt][1]), "=r"(a[mt][2]), "=r"(a[mt][3])
                             : "r"(aAddr[mt] + soff + k0 * 2));
            #pragma unroll
            for (int p = 0; p < 4; p++)
                asm volatile("ldmatrix.sync.aligned.m8n8.x4.shared.b16 {%0,%1,%2,%3}, [%4];"
                             : "=r"(b[p][0]), "=r"(b[p][1]), "=r"(b[p][2]), "=r"(b[p][3])
                             : "r"(bAddr[p] + soff + k0 * 2));
            #pragma unroll
            for (int mt = 0; mt < 2; mt++)
                #pragma unroll
                for (int nt = 0; nt < 8; nt++) {
                    int p = nt >> 1, q = (nt & 1) * 2;
                    asm volatile(
                        "mma.sync.aligned.m16n8k16.row.col.f32.f16.f16.f32 "
                        "{%0,%1,%2,%3}, {%4,%5,%6,%7}, {%8,%9}, {%0,%1,%2,%3};"
                        : "+f"(acc[mt][nt][0]), "+f"(acc[mt][nt][1]),
                          "+f"(acc[mt][nt][2]), "+f"(acc[mt][nt][3])
                        : "r"(a[mt][0]), "r"(a[mt][1]), "r"(a[mt][2]), "r"(a[mt][3]),
                          "r"(b[p][q]), "r"(b[p][q + 1]));
                }
        }
        __syncthreads();
        if (kc + 2 < 10) fill(kc + 2, s);
    }

    // ---- epilogue: bias + relu ----
    const int rbase = lane >> 2;
    const int col2  = (lane & 3) * 2;
    #pragma unroll
    for (int mt = 0; mt < 2; mt++) {
        #pragma unroll
        for (int hh = 0; hh < 2; hh++) {
            int gm = m0 + wm * 32 + mt * 16 + rbase + hh * 8;
            if (gm >= M) continue;
            #pragma unroll
            for (int nt = 0; nt < 8; nt++) {
                int gn = wn * 64 + nt * 8 + col2;
                float2 o;
                o.x = fmaxf(acc[mt][nt][hh * 2]     + bias[gn],     0.f);
                o.y = fmaxf(acc[mt][nt][hh * 2 + 1] + bias[gn + 1], 0.f);
                *(float2*)(out + (size_t)gm * HD + gn) = o;
            }
        }
    }
}

extern "C" void kernel_launch(void* const* d_in, const int* in_sizes, int n_in,
                              void* d_out, int out_size)
{
    const float* h       = (const float*)d_in[0];
    const float* norm    = (const float*)d_in[1];
    const float* basis_w = (const float*)d_in[2];
    const float* w_comp  = (const float*)d_in[3];
    const float* loop_w  = (const float*)d_in[4];
    const float* bias    = (const float*)d_in[5];
    const int*   src     = (const int*)d_in[6];
    const int*   dst     = (const int*)d_in[7];
    const int*   etype   = (const int*)d_in[8];
    float* out = (float*)d_out;

    int M = in_sizes[0] / HD;   // 50000
    int E = in_sizes[6];        // 800000

    cudaFuncSetAttribute(gemm2_k, cudaFuncAttributeMaxDynamicSharedMemorySize, SMEM_BYTES);

    prep_k<<<(NP * 32 + 255) / 256, 256>>>(h, basis_w, loop_w, M);
    hist_k<<<((E + 3) / 4 + 255) / 256, 256>>>(dst, E);
    scan_k<<<NBLK, 256>>>();
    bucket_k<<<((E + 1) / 2 + 255) / 256, 256>>>(norm, src, dst, etype, E);
    accum_k<<<(NP * 32 + 255) / 256, 256>>>(w_comp);
    gemm2_k<<<NP / 128, 256, SMEM_BYTES>>>(bias, out, M);
}

// round 16
// speedup vs baseline: 1.1264x; 1.0155x over previous
#include <cuda_runtime.h>
#include <cuda_fp16.h>
#include <cstdint>

// RGCN basis layer, scatter-first ordering (round-15 base; 16B cp.async fills):
//   agg[v, b, :] = sum_{e: dst=v} (w_comp[etype_e, b] * norm_e) * h[src_e]
//   out = relu( [agg | h] @ [W0;W1;W2;W3;loop_w] + bias )
// Stages:
//   prep:   h->fp16, Wh fp16 n-major stack, zero counts+total
//   hist:   per-dst counts + per-edge rank (8 edges/thread)
//   scan:   block-local exclusive scan + atomic block base
//   bucket: ONE 8B record {src|etype<<16, norm_f32} per edge (2 edges/thread)
//   accum:  warp/dst register accumulation; w_comp in smem; coeffs fp32
//   gemm2:  fp16 mma m16n8k16, 128x128 tile, 2-stage cp.async.cg(16B), 2 blk/SM

#define HD 128
#define NB 4
#define NREL 40
#define NNODES 50000
#define NEDGES 800000
#define NP 50176            // 392 * 128 = 196 * 256
#define NBLK 196
#define KTOT 640
#define SMSH 72             // smem row stride in halves (144B) -> conflict-free

__device__ __half g_h16[(size_t)NP * HD];        // 12.8 MB
__device__ __half g_agg[(size_t)NP * 512];       // 51.4 MB
__device__ __half g_Wh[HD * KTOT];               // fp16 n-major weights

// CSR scratch
__device__ int  g_cnt[NP];
__device__ int  g_off[NP];
__device__ int  g_total;
__device__ int  g_rank[NEDGES];
__device__ int2 g_edge8[NEDGES];   // {src | etype<<16, norm bits}

static __device__ __forceinline__ uint32_t smem_u32(const void* p) {
    uint32_t a;
    asm("{ .reg .u64 t; cvta.to.shared.u64 t, %1; cvt.u32.u64 %0, t; }" : "=r"(a) : "l"(p));
    return a;
}

#define CP_ASYNC16(sa, gp) \
    asm volatile("cp.async.cg.shared.global [%0], [%1], 16;" :: "r"(sa), "l"(gp))
#define CP_COMMIT() asm volatile("cp.async.commit_group;")

struct alignas(8) Half4 { __half2 lo, hi; };

// ---------------------------------------------------------------------------
// prep: h16 convert + weight stack + zero counts
// ---------------------------------------------------------------------------
__global__ __launch_bounds__(256) void prep_k(
    const float* __restrict__ h,
    const float* __restrict__ basis_w,
    const float* __restrict__ loop_w,
    int M)
{
    int idx = blockIdx.x * blockDim.x + threadIdx.x;

    if (idx < NP * 32) {
        int m = idx >> 5;
        float4 v = (m < M) ? *(const float4*)(h + (size_t)idx * 4)
                           : make_float4(0.f, 0.f, 0.f, 0.f);
        Half4 o;
        o.lo = __floats2half2_rn(v.x, v.y);
        o.hi = __floats2half2_rn(v.z, v.w);
        *(Half4*)(g_h16 + (size_t)idx * 4) = o;
    }
    if (idx < HD * KTOT) {          // Wh[n][k]
        int n = idx / KTOT;
        int k = idx - n * KTOT;
        float v;
        if (k < NB * HD) {
            int b = k >> 7, kk = k & 127;
            v = basis_w[(size_t)b * HD * HD + (size_t)kk * HD + n];
        } else {
            v = loop_w[(size_t)(k - NB * HD) * HD + n];
        }
        g_Wh[idx] = __float2half_rn(v);
    }
    if (idx < NP) g_cnt[idx] = 0;
    if (idx == 0) g_total = 0;
}

// ---------------------------------------------------------------------------
// hist: counts + per-edge rank, 8 edges/thread for atomic MLP
// ---------------------------------------------------------------------------
__global__ __launch_bounds__(256) void hist_k(const int* __restrict__ dst, int E)
{
    int e0 = (blockIdx.x * blockDim.x + threadIdx.x) * 8;
    if (e0 + 7 < E) {
        int4 d0 = *(const int4*)(dst + e0);
        int4 d1 = *(const int4*)(dst + e0 + 4);
        int r0 = atomicAdd(&g_cnt[d0.x], 1);
        int r1 = atomicAdd(&g_cnt[d0.y], 1);
        int r2 = atomicAdd(&g_cnt[d0.z], 1);
        int r3 = atomicAdd(&g_cnt[d0.w], 1);
        int r4 = atomicAdd(&g_cnt[d1.x], 1);
        int r5 = atomicAdd(&g_cnt[d1.y], 1);
        int r6 = atomicAdd(&g_cnt[d1.z], 1);
        int r7 = atomicAdd(&g_cnt[d1.w], 1);
        *(int4*)(g_rank + e0)     = make_int4(r0, r1, r2, r3);
        *(int4*)(g_rank + e0 + 4) = make_int4(r4, r5, r6, r7);
    } else {
        for (int e = e0; e < E; e++)
            g_rank[e] = atomicAdd(&g_cnt[dst[e]], 1);
    }
}

// ---------------------------------------------------------------------------
// scan: block-local exclusive scan; base via atomicAdd (order arbitrary)
// ---------------------------------------------------------------------------
__global__ __launch_bounds__(256) void scan_k()
{
    __shared__ int s[256];
    __shared__ int blockBase;
    int t = threadIdx.x;
    int gid = blockIdx.x * 256 + t;
    int v = g_cnt[gid];
    s[t] = v;
    __syncthreads();
    #pragma unroll
    for (int d = 1; d < 256; d <<= 1) {
        int x = (t >= d) ? s[t - d] : 0;
        __syncthreads();
        s[t] += x;
        __syncthreads();
    }
    if (t == 255) blockBase = atomicAdd(&g_total, s[255]);
    __syncthreads();
    g_off[gid] = blockBase + s[t] - v;
}

// ---------------------------------------------------------------------------
// bucket: one 8B record {src|etype<<16, norm bits} per edge, 2 edges/thread
// ---------------------------------------------------------------------------
__global__ __launch_bounds__(256) void bucket_k(
    const float* __restrict__ norm,
    const int* __restrict__ src,
    const int* __restrict__ dst,
    const int* __restrict__ etype,
    int E)
{
    int e0 = (blockIdx.x * blockDim.x + threadIdx.x) * 2;
    if (e0 + 1 < E) {
        int2   d  = *(const int2*)(dst + e0);
        int2   sc = *(const int2*)(src + e0);
        int2   tt = *(const int2*)(etype + e0);
        float2 nm = *(const float2*)(norm + e0);
        int2   rk = *(const int2*)(g_rank + e0);
        int o0 = g_off[d.x];
        int o1 = g_off[d.y];
        g_edge8[o0 + rk.x] = make_int2(sc.x | (tt.x << 16), __float_as_int(nm.x));
        g_edge8[o1 + rk.y] = make_int2(sc.y | (tt.y << 16), __float_as_int(nm.y));
    } else {
        for (int e = e0; e < E; e++) {
            int dd = dst[e];
            g_edge8[g_off[dd] + g_rank[e]] =
                make_int2(src[e] | (etype[e] << 16), __float_as_int(norm[e]));
        }
    }
}

// ---------------------------------------------------------------------------
// accum: warp per dst node; w_comp in smem; fp32 coeffs; 4-edge unroll.
// ---------------------------------------------------------------------------
__global__ __launch_bounds__(256) void accum_k(const float* __restrict__ w_comp)
{
    __shared__ float ws[NREL * NB];
    if (threadIdx.x < NREL * NB) ws[threadIdx.x] = w_comp[threadIdx.x];
    __syncthreads();

    int v    = (blockIdx.x * blockDim.x + threadIdx.x) >> 5;
    int lane = threadIdx.x & 31;
    if (v >= NP) return;

    int base = g_off[v];
    int deg  = g_cnt[v];

    float4 a0 = {0.f, 0.f, 0.f, 0.f};
    float4 a1 = a0, a2 = a0, a3 = a0;

    const __half* Hl = g_h16 + lane * 4;

    int i = 0;
    for (; i + 4 <= deg; i += 4) {
        int2 r0 = g_edge8[base + i];
        int2 r1 = g_edge8[base + i + 1];
        int2 r2 = g_edge8[base + i + 2];
        int2 r3 = g_edge8[base + i + 3];
        Half4 hv0 = *(const Half4*)(Hl + (size_t)(r0.x & 0xFFFF) * HD);
        Half4 hv1 = *(const Half4*)(Hl + (size_t)(r1.x & 0xFFFF) * HD);
        Half4 hv2 = *(const Half4*)(Hl + (size_t)(r2.x & 0xFFFF) * HD);
        Half4 hv3 = *(const Half4*)(Hl + (size_t)(r3.x & 0xFFFF) * HD);
        #pragma unroll
        for (int j = 0; j < 4; j++) {
            int2 rr = (j == 0) ? r0 : (j == 1) ? r1 : (j == 2) ? r2 : r3;
            Half4 hh = (j == 0) ? hv0 : (j == 1) ? hv1 : (j == 2) ? hv2 : hv3;
            int t = rr.x >> 16;
            float nm = __int_as_float(rr.y);
            const float* wr = ws + t * NB;
            float c0 = wr[0] * nm, c1 = wr[1] * nm, c2 = wr[2] * nm, c3 = wr[3] * nm;
            float2 lo = __half22float2(hh.lo), hi = __half22float2(hh.hi);
            a0.x += c0 * lo.x; a0.y += c0 * lo.y; a0.z += c0 * hi.x; a0.w += c0 * hi.y;
            a1.x += c1 * lo.x; a1.y += c1 * lo.y; a1.z += c1 * hi.x; a1.w += c1 * hi.y;
            a2.x += c2 * lo.x; a2.y += c2 * lo.y; a2.z += c2 * hi.x; a2.w += c2 * hi.y;
            a3.x += c3 * lo.x; a3.y += c3 * lo.y; a3.z += c3 * hi.x; a3.w += c3 * hi.y;
        }
    }
    for (; i < deg; i++) {
        int2 rr = g_edge8[base + i];
        Half4 hh = *(const Half4*)(Hl + (size_t)(rr.x & 0xFFFF) * HD);
        int t = rr.x >> 16;
        float nm = __int_as_float(rr.y);
        const float* wr = ws + t * NB;
        float c0 = wr[0] * nm, c1 = wr[1] * nm, c2 = wr[2] * nm, c3 = wr[3] * nm;
        float2 lo = __half22float2(hh.lo), hi = __half22float2(hh.hi);
        a0.x += c0 * lo.x; a0.y += c0 * lo.y; a0.z += c0 * hi.x; a0.w += c0 * hi.y;
        a1.x += c1 * lo.x; a1.y += c1 * lo.y; a1.z += c1 * hi.x; a1.w += c1 * hi.y;
        a2.x += c2 * lo.x; a2.y += c2 * lo.y; a2.z += c2 * hi.x; a2.w += c2 * hi.y;
        a3.x += c3 * lo.x; a3.y += c3 * lo.y; a3.z += c3 * hi.x; a3.w += c3 * hi.y;
    }

    __half* ap = g_agg + (size_t)v * 512 + lane * 4;
    Half4 o;
    o.lo = __floats2half2_rn(a0.x, a0.y); o.hi = __floats2half2_rn(a0.z, a0.w);
    *(Half4*)(ap + 0)   = o;
    o.lo = __floats2half2_rn(a1.x, a1.y); o.hi = __floats2half2_rn(a1.z, a1.w);
    *(Half4*)(ap + 128) = o;
    o.lo = __floats2half2_rn(a2.x, a2.y); o.hi = __floats2half2_rn(a2.z, a2.w);
    *(Half4*)(ap + 256) = o;
    o.lo = __floats2half2_rn(a3.x, a3.y); o.hi = __floats2half2_rn(a3.z, a3.w);
    *(Half4*)(ap + 384) = o;
}

// ---------------------------------------------------------------------------
// gemm2: fp16 mma m16n8k16, 2-stage cp.async.cg(16B) pipeline, 2 blocks/SM.
// Block 128m x 128n, K=640 in 64-chunks; 8 warps = 4m x 2n.
// ---------------------------------------------------------------------------
#define STAGE_HALVES (2 * 128 * SMSH)              // A + B per stage
#define STAGE_BYTES  (STAGE_HALVES * 2)
#define SMEM_BYTES   (2 * STAGE_BYTES)             // 73728

__global__ __launch_bounds__(256, 2) void gemm2_k(
    const float* __restrict__ bias,
    float* __restrict__ out,
    int M)
{
    extern __shared__ __half smh[];

    const int tid  = threadIdx.x;
    const int m0   = blockIdx.x * 128;
    const int lane = tid & 31;
    const int w    = tid >> 5;
    const int wm   = w & 3;
    const int wn   = w >> 2;

    // 16B fill indexing: 128 rows x 8 (16B units) = 1024 slots, 4 per thread
    const int fr = tid >> 3;     // 0..31 base row, step 32
    const int fq = tid & 7;      // 16B unit within 64-half row (8 halves each)

    uint32_t sA0 = smem_u32(smh) + (uint32_t)(fr * SMSH + fq * 8) * 2;
    uint32_t sB0 = sA0 + (uint32_t)(128 * SMSH) * 2;

    auto fill = [&](int kc, int s) {
        uint32_t sa = sA0 + s * STAGE_BYTES;
        uint32_t sb = sB0 + s * STAGE_BYTES;
        if (kc < 8) {
            const __half* ap = g_agg + (size_t)(m0 + fr) * 512 + kc * 64 + fq * 8;
            #pragma unroll
            for (int i = 0; i < 4; i++)
                CP_ASYNC16(sa + i * 32 * SMSH * 2, ap + (size_t)i * 32 * 512);
        } else {
            const __half* ap = g_h16 + (size_t)(m0 + fr) * HD + (kc * 64 - 512) + fq * 8;
            #pragma unroll
            for (int i = 0; i < 4; i++)
                CP_ASYNC16(sa + i * 32 * SMSH * 2, ap + (size_t)i * 32 * HD);
        }
        const __half* bp = g_Wh + (size_t)fr * KTOT + kc * 64 + fq * 8;
        #pragma unroll
        for (int i = 0; i < 4; i++)
            CP_ASYNC16(sb + i * 32 * SMSH * 2, bp + (size_t)i * 32 * KTOT);
        CP_COMMIT();
    };

    const int arow  = (lane & 7) + ((lane >> 3) & 1) * 8;
    const int akoff = (lane & 16) ? 8 : 0;
    const int brow  = (lane & 7) + ((lane & 16) ? 8 : 0);
    const int bkoff = (lane & 8) ? 8 : 0;

    uint32_t aAddr[2], bAddr[4];
    #pragma unroll
    for (int mt = 0; mt < 2; mt++)
        aAddr[mt] = smem_u32(smh + (wm * 32 + mt * 16 + arow) * SMSH + akoff);
    #pragma unroll
    for (int p = 0; p < 4; p++)
        bAddr[p] = smem_u32(smh + 128 * SMSH + (wn * 64 + p * 16 + brow) * SMSH + bkoff);

    float acc[2][8][4];
    #pragma unroll
    for (int mt = 0; mt < 2; mt++)
        #pragma unroll
        for (int nt = 0; nt < 8; nt++)
            #pragma unroll
            for (int q = 0; q < 4; q++) acc[mt][nt][q] = 0.f;

    fill(0, 0);
    fill(1, 1);

    for (int kc = 0; kc < 10; kc++) {
        int s = kc & 1;
        if (kc == 9) { asm volatile("cp.async.wait_group 0;"); }
        else         { asm volatile("cp.async.wait_group 1;"); }
        __syncthreads();

        uint32_t soff = (uint32_t)s * STAGE_BYTES;
        #pragma unroll
        for (int k0 = 0; k0 < 64; k0 += 16) {
            uint32_t a[2][4], b[4][4];
            #pragma unroll
            for (int mt = 0; mt < 2; mt++)
                asm volatile("ldmatrix.sync.aligned.m8n8.x4.shared.b16 {%0,%1,%2,%3}, [%4];"
                             : "=r"(a[mt][0]), "=r"(a[mt][1]), "=r"(a[mt][2]), "=r"(a[mt][3])
                             : "r"(aAddr[mt] + soff + k0 * 2));
            #pragma unroll
            for (int p = 0; p < 4; p++)
                asm volatile("ldmatrix.sync.aligned.m8n8.x4.shared.b16 {%0,%1,%2,%3}, [%4];"
                             : "=r"(b[p][0]), "=r"(b[p][1]), "=r"(b[p][2]), "=r"(b[p][3])
                             : "r"(bAddr[p] + soff + k0 * 2));
            #pragma unroll
            for (int mt = 0; mt < 2; mt++)
                #pragma unroll
                for (int nt = 0; nt < 8; nt++) {
                    int p = nt >> 1, q = (nt & 1) * 2;
                    asm volatile(
                        "mma.sync.aligned.m16n8k16.row.col.f32.f16.f16.f32 "
                        "{%0,%1,%2,%3}, {%4,%5,%6,%7}, {%8,%9}, {%0,%1,%2,%3};"
                        : "+f"(acc[mt][nt][0]), "+f"(acc[mt][nt][1]),
                          "+f"(acc[mt][nt][2]), "+f"(acc[mt][nt][3])
                        : "r"(a[mt][0]), "r"(a[mt][1]), "r"(a[mt][2]), "r"(a[mt][3]),
                          "r"(b[p][q]), "r"(b[p][q + 1]));
                }
        }
        __syncthreads();
        if (kc + 2 < 10) fill(kc + 2, s);
    }

    // ---- epilogue: bias + relu ----
    const int rbase = lane >> 2;
    const int col2  = (lane & 3) * 2;
    #pragma unroll
    for (int mt = 0; mt < 2; mt++) {
        #pragma unroll
        for (int hh = 0; hh < 2; hh++) {
            int gm = m0 + wm * 32 + mt * 16 + rbase + hh * 8;
            if (gm >= M) continue;
            #pragma unroll
            for (int nt = 0; nt < 8; nt++) {
                int gn = wn * 64 + nt * 8 + col2;
                float2 o;
                o.x = fmaxf(acc[mt][nt][hh * 2]     + bias[gn],     0.f);
                o.y = fmaxf(acc[mt][nt][hh * 2 + 1] + bias[gn + 1], 0.f);
                *(float2*)(out + (size_t)gm * HD + gn) = o;
            }
        }
    }
}

extern "C" void kernel_launch(void* const* d_in, const int* in_sizes, int n_in,
                              void* d_out, int out_size)
{
    const float* h       = (const float*)d_in[0];
    const float* norm    = (const float*)d_in[1];
    const float* basis_w = (const float*)d_in[2];
    const float* w_comp  = (const float*)d_in[3];
    const float* loop_w  = (const float*)d_in[4];
    const float* bias    = (const float*)d_in[5];
    const int*   src     = (const int*)d_in[6];
    const int*   dst     = (const int*)d_in[7];
    const int*   etype   = (const int*)d_in[8];
    float* out = (float*)d_out;

    int M = in_sizes[0] / HD;   // 50000
    int E = in_sizes[6];        // 800000

    cudaFuncSetAttribute(gemm2_k, cudaFuncAttributeMaxDynamicSharedMemorySize, SMEM_BYTES);

    prep_k<<<(NP * 32 + 255) / 256, 256>>>(h, basis_w, loop_w, M);
    hist_k<<<((E + 7) / 8 + 255) / 256, 256>>>(dst, E);
    scan_k<<<NBLK, 256>>>();
    bucket_k<<<((E + 1) / 2 + 255) / 256, 256>>>(norm, src, dst, etype, E);
    accum_k<<<(NP * 32 + 255) / 256, 256>>>(w_comp);
    gemm2_k<<<NP / 128, 256, SMEM_BYTES>>>(bias, out, M);
}